// round 14
// baseline (speedup 1.0000x reference)
#include <cuda_runtime.h>
#include <cstdint>

// out[b, n, :] = (cnn[b] @ Wkv[:, 768:1536]) @ Wp + bp   (independent of n)
// image_patches and Wq are dead: softmax over kv_len=1 -> attn == 1.
//
// 3 launches:
//   gemm1: 384 CTAs x 128 thr (12 n-tiles of 64 x 32 k-splits of 64),
//          one-phase smem staging, 4m x 8n micro-tile (1.5 B LDS per FMA),
//          red.v4 -> g_v (zero on entry: static init call 1, re-zeroed by
//          bcast each call). Prologue: g_y = bias.
//   gemm2: 192 CTAs x 128 thr (12 n-tiles x 16 k-splits of 48), same body,
//          red.v4 -> bias-preloaded g_y.
//   bcast: 576 CTAs x 512 thr, 8 TMA bulk stores of 24 KB; zeroes g_v at end.

#define B_SZ   64
#define N_SEQ  576
#define C_DIM  768
#define K1     2048
#define LDKV   1536

#define NT1    12              // gemm1: 12 n-tiles of 64
#define KS1    32              // gemm1: 32 k-splits of 64 -> 384 blocks
#define KC1    64
#define NT2    12              // gemm2: 12 n-tiles of 64
#define KS2    16              // gemm2: 16 k-splits of 48 -> 192 blocks
#define KC2    48

__device__ float g_v[B_SZ * C_DIM];   // zero on entry to every call
__device__ float g_y[B_SZ * C_DIM];   // set to bias by gemm1 every call

// ---- packed f32x2 (FFMA2) ----
__device__ __forceinline__ unsigned long long pack2(float x) {
    unsigned long long r; unsigned xi = __float_as_uint(x);
    asm("mov.b64 %0, {%1, %1};" : "=l"(r) : "r"(xi));
    return r;
}
__device__ __forceinline__ void fma2(unsigned long long& d,
                                     unsigned long long a, unsigned long long b) {
    asm("fma.rn.f32x2 %0, %1, %2, %0;" : "+l"(d) : "l"(a), "l"(b));
}
__device__ __forceinline__ float2 u2f(unsigned long long u) {
    float2 f; asm("mov.b64 {%0, %1}, %2;" : "=f"(f.x), "=f"(f.y) : "l"(u));
    return f;
}
// Vector reduction: 1 LTS atomic op for 4 floats (sm_90+).
__device__ __forceinline__ void redg_add4(float* p, float a, float b, float c, float d) {
    asm volatile("red.global.add.v4.f32 [%0], {%1, %2, %3, %4};"
                 :: "l"(p), "f"(a), "f"(b), "f"(c), "f"(d) : "memory");
}
__device__ __forceinline__ uint32_t smem_u32(const void* p) {
    uint32_t a;
    asm("{ .reg .u64 t; cvta.to.shared.u64 t, %1; cvt.u32.u64 %0, t; }" : "=r"(a) : "l"(p));
    return a;
}

// ---------------------------------------------------------------------------
// One-phase 64x64 tile GEMM, 128 threads, 4m x 8n micro-tile:
// stage FULL K-chunk in smem (batched LDG.128, MLP = 2*NV/128), one sync,
// then an uninterrupted KCHUNK-step FFMA2 loop.
// Per k-step per thread: LDS.128 (A) + 2x LDS.128 (B) + 4 packs + 16 FFMA2
// = 48 B LDS per 32 FMA = 1.5 B/FMA.
// ---------------------------------------------------------------------------
template<int KCHUNK>
__device__ __forceinline__ void gemm_tile_128(
    const float* __restrict__ A, int lda,     // A[64 x KCHUNK], row-major
    const float* __restrict__ Bm, int ldb,    // B[KCHUNK x 64], row-major
    float (*As)[68],                          // [KCHUNK][68] transposed A
    float (*Bs)[64],                          // [KCHUNK][64]
    unsigned long long acc[4][4])
{
    const int tid = threadIdx.x;
    constexpr int NV = (64 * KCHUNK) / 4;     // float4 per operand
    constexpr int PT = NV / 128;              // per-thread float4 count

    float4 aR[PT], bR[PT];
    #pragma unroll
    for (int i = 0; i < PT; ++i) {
        int idx = tid + i * 128;
        int am = idx / (KCHUNK / 4);
        int ak = (idx % (KCHUNK / 4)) * 4;
        aR[i] = *(const float4*)&A[am * lda + ak];
        int bk = idx >> 4;
        int bn = (idx & 15) * 4;
        bR[i] = *(const float4*)&Bm[bk * ldb + bn];
    }
    #pragma unroll
    for (int i = 0; i < PT; ++i) {
        int idx = tid + i * 128;
        int am = idx / (KCHUNK / 4);
        int ak = (idx % (KCHUNK / 4)) * 4;
        As[ak + 0][am] = aR[i].x; As[ak + 1][am] = aR[i].y;
        As[ak + 2][am] = aR[i].z; As[ak + 3][am] = aR[i].w;
        int bk = idx >> 4;
        int bn = (idx & 15) * 4;
        *(float4*)&Bs[bk][bn] = bR[i];
    }
    __syncthreads();

    const int tx = tid & 7;        // 8 n-groups of 8
    const int ty = tid >> 3;       // 16 m-groups of 4
    #pragma unroll 16
    for (int k = 0; k < KCHUNK; ++k) {
        float4 a = *(const float4*)&As[k][ty * 4];
        ulonglong2 b0 = *(const ulonglong2*)&Bs[k][tx * 8];
        ulonglong2 b1 = *(const ulonglong2*)&Bs[k][tx * 8 + 4];
        unsigned long long a0 = pack2(a.x), a1 = pack2(a.y);
        unsigned long long a2 = pack2(a.z), a3 = pack2(a.w);
        fma2(acc[0][0], a0, b0.x); fma2(acc[0][1], a0, b0.y);
        fma2(acc[0][2], a0, b1.x); fma2(acc[0][3], a0, b1.y);
        fma2(acc[1][0], a1, b0.x); fma2(acc[1][1], a1, b0.y);
        fma2(acc[1][2], a1, b1.x); fma2(acc[1][3], a1, b1.y);
        fma2(acc[2][0], a2, b0.x); fma2(acc[2][1], a2, b0.y);
        fma2(acc[2][2], a2, b1.x); fma2(acc[2][3], a2, b1.y);
        fma2(acc[3][0], a3, b0.x); fma2(acc[3][1], a3, b0.y);
        fma2(acc[3][2], a3, b1.x); fma2(acc[3][3], a3, b1.y);
    }
}

// Shared epilogue: 4 rows x 8 cols per thread -> 8x red.v4.
__device__ __forceinline__ void epilogue_red(
    float* dst, int n0, unsigned long long acc[4][4])
{
    const int tid = threadIdx.x;
    const int tx = tid & 7, ty = tid >> 3;
    #pragma unroll
    for (int i = 0; i < 4; ++i) {
        float2 f0 = u2f(acc[i][0]), f1 = u2f(acc[i][1]);
        float2 f2 = u2f(acc[i][2]), f3 = u2f(acc[i][3]);
        float* p = dst + (ty * 4 + i) * C_DIM + n0 + tx * 8;
        redg_add4(p,     f0.x, f0.y, f1.x, f1.y);
        redg_add4(p + 4, f2.x, f2.y, f3.x, f3.y);
    }
}

// GEMM1: cnn[64,2048] @ Wkv[:,768:1536], 384 blocks x 128 thr -> g_v.
// Prologue (first 192 blocks): g_y = bias.
__global__ void __launch_bounds__(128)
gemm1_kernel(const float* __restrict__ cnn, const float* __restrict__ Wkv,
             const float* __restrict__ bp)
{
    __shared__ float As[KC1][68];   // 17.4 KB
    __shared__ float Bs[KC1][64];   // 16 KB

    const int tid = threadIdx.x;
    if (blockIdx.x < 192 && tid < 64) {
        int idx = blockIdx.x * 64 + tid;                  // 12288 float4 of g_y
        ((float4*)g_y)[idx] = ((const float4*)bp)[idx % (C_DIM / 4)];
    }

    int ntile = blockIdx.x % NT1;
    int split = blockIdx.x / NT1;
    int n0 = ntile * 64;

    unsigned long long acc[4][4];
    #pragma unroll
    for (int i = 0; i < 4; ++i)
        #pragma unroll
        for (int j = 0; j < 4; ++j) acc[i][j] = 0ull;

    gemm_tile_128<KC1>(cnn + split * KC1, K1,
                       Wkv + (size_t)(split * KC1) * LDKV + C_DIM + n0, LDKV,
                       As, Bs, acc);

    epilogue_red(g_v, n0, acc);
}

// GEMM2: v[64,768] @ Wp, 192 blocks x 128 thr, red.v4 into g_y (bias preloaded).
__global__ void __launch_bounds__(128)
gemm2_kernel(const float* __restrict__ Wp)
{
    __shared__ float As[KC2][68];   // 13 KB
    __shared__ float Bs[KC2][64];   // 12 KB

    int ntile = blockIdx.x % NT2;
    int split = blockIdx.x / NT2;
    int n0 = ntile * 64;

    unsigned long long acc[4][4];
    #pragma unroll
    for (int i = 0; i < 4; ++i)
        #pragma unroll
        for (int j = 0; j < 4; ++j) acc[i][j] = 0ull;

    gemm_tile_128<KC2>(g_v + split * KC2, C_DIM,
                       Wp + (size_t)(split * KC2) * C_DIM + n0, C_DIM,
                       As, Bs, acc);

    epilogue_red(g_y, n0, acc);
}

// Broadcast g_y over N=576 via TMA bulk stores; zero g_v for the next call.
// 576 blocks x 512 threads: b = bx/9, 64 rows per block; stage 8 replicated
// rows (24 KB) once, then 8 bulk stores of 24 KB (8 rows each).
__global__ void __launch_bounds__(512)
bcast_kernel(float* __restrict__ out)
{
    __shared__ __align__(16) float ys[8 * C_DIM];   // 24 KB

    int b     = blockIdx.x / 9;
    int chunk = blockIdx.x % 9;
    const int tid = threadIdx.x;

    const float4* ysrc = (const float4*)(g_y + b * C_DIM);
    #pragma unroll
    for (int i = tid; i < 8 * (C_DIM / 4); i += 512)
        ((float4*)ys)[i] = ysrc[i % (C_DIM / 4)];
    __syncthreads();
    asm volatile("fence.proxy.async.shared::cta;" ::: "memory");

    if (tid < 8) {
        uint32_t s = smem_u32(ys);
        float* g = out + ((size_t)b * N_SEQ + chunk * 64 + tid * 8) * C_DIM;
        asm volatile("cp.async.bulk.global.shared::cta.bulk_group [%0], [%1], %2;"
                     :: "l"(g), "r"(s), "n"(8 * C_DIM * 4) : "memory");
        asm volatile("cp.async.bulk.commit_group;" ::: "memory");
        asm volatile("cp.async.bulk.wait_group 0;" ::: "memory");
    }

    // zero g_v for the next call (first 192 blocks cover 12288 float4)
    if (blockIdx.x < 192 && tid < 64) {
        ((float4*)g_v)[blockIdx.x * 64 + tid] = make_float4(0.f, 0.f, 0.f, 0.f);
    }
}

extern "C" void kernel_launch(void* const* d_in, const int* in_sizes, int n_in,
                              void* d_out, int out_size)
{
    (void)in_sizes; (void)n_in; (void)out_size;
    // Inputs: image_patches, cnn_feature_vector, Wq, Wkv, Wp, bp
    const float* cnn = (const float*)d_in[1];
    const float* Wkv = (const float*)d_in[3];
    const float* Wp  = (const float*)d_in[4];
    const float* bp  = (const float*)d_in[5];
    float* out = (float*)d_out;

    gemm1_kernel<<<NT1 * KS1, 128>>>(cnn, Wkv, bp);   // 384 blocks
    gemm2_kernel<<<NT2 * KS2, 128>>>(Wp);             // 192 blocks
    bcast_kernel<<<B_SZ * 9, 512>>>(out);             // 576 blocks
}

// round 15
// speedup vs baseline: 1.1695x; 1.1695x over previous
#include <cuda_runtime.h>
#include <cstdint>

// out[b, n, :] = (cnn[b] @ Wkv[:, 768:1536]) @ Wp + bp   (independent of n)
// image_patches and Wq are dead: softmax over kv_len=1 -> attn == 1.
//
// 3 launches chained with PDL (programmatic dependent launch):
//   gemm1: 384 CTAs x 256 thr (12 n-tiles x 32 k-splits of 64), one-phase
//          smem staging, red.v4 -> g_v (zero on entry: static init call 1,
//          re-zeroed by bcast each call). Prologue: g_y = bias.
//   gemm2: 192 CTAs x 256 thr (12 n-tiles x 16 k-splits of 48); loads Wp into
//          registers BEFORE cudaGridDependencySynchronize() (independent of
//          g_v), then g_v, red.v4 -> bias-preloaded g_y.
//   bcast: 576 CTAs x 512 thr, 8 TMA bulk stores of 24 KB; zeroes g_v at end.

#define B_SZ   64
#define N_SEQ  576
#define C_DIM  768
#define K1     2048
#define LDKV   1536

#define NT1    12              // gemm1: 12 n-tiles of 64
#define KS1    32              // gemm1: 32 k-splits of 64 -> 384 blocks
#define KC1    64
#define NT2    12              // gemm2: 12 n-tiles of 64
#define KS2    16              // gemm2: 16 k-splits of 48 -> 192 blocks
#define KC2    48

__device__ float g_v[B_SZ * C_DIM];   // zero on entry to every call
__device__ float g_y[B_SZ * C_DIM];   // set to bias by gemm1 every call

// ---- packed f32x2 (FFMA2) ----
__device__ __forceinline__ unsigned long long pack2(float x) {
    unsigned long long r; unsigned xi = __float_as_uint(x);
    asm("mov.b64 %0, {%1, %1};" : "=l"(r) : "r"(xi));
    return r;
}
__device__ __forceinline__ void fma2(unsigned long long& d,
                                     unsigned long long a, unsigned long long b) {
    asm("fma.rn.f32x2 %0, %1, %2, %0;" : "+l"(d) : "l"(a), "l"(b));
}
__device__ __forceinline__ float2 u2f(unsigned long long u) {
    float2 f; asm("mov.b64 {%0, %1}, %2;" : "=f"(f.x), "=f"(f.y) : "l"(u));
    return f;
}
// Vector reduction: 1 LTS atomic op for 4 floats (sm_90+).
__device__ __forceinline__ void redg_add4(float* p, float a, float b, float c, float d) {
    asm volatile("red.global.add.v4.f32 [%0], {%1, %2, %3, %4};"
                 :: "l"(p), "f"(a), "f"(b), "f"(c), "f"(d) : "memory");
}
__device__ __forceinline__ uint32_t smem_u32(const void* p) {
    uint32_t a;
    asm("{ .reg .u64 t; cvta.to.shared.u64 t, %1; cvt.u32.u64 %0, t; }" : "=r"(a) : "l"(p));
    return a;
}

// ---------------------------------------------------------------------------
// FFMA2 compute loop for the 64x64 tile (4m x 4n per thread, 256 threads).
// ---------------------------------------------------------------------------
template<int KCHUNK>
__device__ __forceinline__ void compute_loop(
    const float (*As)[68], const float (*Bs)[64], unsigned long long acc[4][2])
{
    const int tid = threadIdx.x;
    const int tx = tid & 15, ty = tid >> 4;
    #pragma unroll 16
    for (int k = 0; k < KCHUNK; ++k) {
        float4 a = *(const float4*)&As[k][ty * 4];
        ulonglong2 b = *(const ulonglong2*)&Bs[k][tx * 4];
        unsigned long long a0 = pack2(a.x), a1 = pack2(a.y);
        unsigned long long a2 = pack2(a.z), a3 = pack2(a.w);
        fma2(acc[0][0], a0, b.x); fma2(acc[0][1], a0, b.y);
        fma2(acc[1][0], a1, b.x); fma2(acc[1][1], a1, b.y);
        fma2(acc[2][0], a2, b.x); fma2(acc[2][1], a2, b.y);
        fma2(acc[3][0], a3, b.x); fma2(acc[3][1], a3, b.y);
    }
}

// Shared epilogue: 4 rows x 4 cols per thread -> 4x red.v4.
__device__ __forceinline__ void epilogue_red(
    float* dst, int n0, unsigned long long acc[4][2])
{
    const int tid = threadIdx.x;
    const int tx = tid & 15, ty = tid >> 4;
    #pragma unroll
    for (int i = 0; i < 4; ++i) {
        float2 f0 = u2f(acc[i][0]);
        float2 f1 = u2f(acc[i][1]);
        redg_add4(dst + (ty * 4 + i) * C_DIM + n0 + tx * 4,
                  f0.x, f0.y, f1.x, f1.y);
    }
}

// GEMM1: cnn[64,2048] @ Wkv[:,768:1536], 384 blocks, red.v4 epilogue -> g_v.
// One-phase staging (round-12 proven). Prologue (first 192 blocks): g_y = bias.
__global__ void __launch_bounds__(256, 2)
gemm1_kernel(const float* __restrict__ cnn, const float* __restrict__ Wkv,
             const float* __restrict__ bp)
{
    __shared__ float As[KC1][68];   // 17.4 KB
    __shared__ float Bs[KC1][64];   // 16 KB

    const int tid = threadIdx.x;
    if (blockIdx.x < 192 && tid < 64) {
        int idx = blockIdx.x * 64 + tid;                  // 12288 float4 of g_y
        ((float4*)g_y)[idx] = ((const float4*)bp)[idx % (C_DIM / 4)];
    }

    int ntile = blockIdx.x % NT1;
    int split = blockIdx.x / NT1;
    int n0 = ntile * 64;
    const float* A  = cnn + split * KC1;                                 // lda K1
    const float* Bm = Wkv + (size_t)(split * KC1) * LDKV + C_DIM + n0;   // ldb LDKV

    constexpr int NV = (64 * KC1) / 4;     // 1024 float4 per operand
    constexpr int PT = NV / 256;           // 4 per thread

    float4 aR[PT], bR[PT];
    #pragma unroll
    for (int i = 0; i < PT; ++i) {
        int idx = tid + i * 256;
        int am = idx / (KC1 / 4);
        int ak = (idx % (KC1 / 4)) * 4;
        aR[i] = *(const float4*)&A[am * K1 + ak];
        int bk = idx >> 4;
        int bn = (idx & 15) * 4;
        bR[i] = *(const float4*)&Bm[bk * LDKV + bn];
    }
    #pragma unroll
    for (int i = 0; i < PT; ++i) {
        int idx = tid + i * 256;
        int am = idx / (KC1 / 4);
        int ak = (idx % (KC1 / 4)) * 4;
        As[ak + 0][am] = aR[i].x; As[ak + 1][am] = aR[i].y;
        As[ak + 2][am] = aR[i].z; As[ak + 3][am] = aR[i].w;
        int bk = idx >> 4;
        int bn = (idx & 15) * 4;
        *(float4*)&Bs[bk][bn] = bR[i];
    }
    __syncthreads();

    unsigned long long acc[4][2];
    #pragma unroll
    for (int i = 0; i < 4; ++i) { acc[i][0] = 0ull; acc[i][1] = 0ull; }
    compute_loop<KC1>(As, Bs, acc);
    epilogue_red(g_v, n0, acc);

    if (tid == 0) cudaTriggerProgrammaticLaunchCompletion();
}

// GEMM2: v[64,768] @ Wp, 192 blocks. PDL: Wp register loads happen BEFORE the
// grid dependency sync (independent of g_v); g_v loads after.
__global__ void __launch_bounds__(256, 2)
gemm2_kernel(const float* __restrict__ Wp)
{
    __shared__ float As[KC2][68];   // 13 KB
    __shared__ float Bs[KC2][64];   // 12 KB

    const int tid = threadIdx.x;
    int ntile = blockIdx.x % NT2;
    int split = blockIdx.x / NT2;
    int n0 = ntile * 64;
    const float* Bm = Wp + (size_t)(split * KC2) * C_DIM + n0;

    constexpr int NV = (64 * KC2) / 4;     // 768 float4 per operand
    constexpr int PT = NV / 256;           // 3 per thread

    // --- pre-sync: load Wp tile (independent of gemm1's output) ---
    float4 bR[PT];
    #pragma unroll
    for (int i = 0; i < PT; ++i) {
        int idx = tid + i * 256;
        int bk = idx >> 4;
        int bn = (idx & 15) * 4;
        bR[i] = *(const float4*)&Bm[bk * C_DIM + bn];
    }

    cudaGridDependencySynchronize();       // wait for gemm1's g_v to be visible

    // --- post-sync: load v tile ---
    const float* A = g_v + split * KC2;
    float4 aR[PT];
    #pragma unroll
    for (int i = 0; i < PT; ++i) {
        int idx = tid + i * 256;
        int am = idx / (KC2 / 4);
        int ak = (idx % (KC2 / 4)) * 4;
        aR[i] = *(const float4*)&A[am * C_DIM + ak];
    }
    #pragma unroll
    for (int i = 0; i < PT; ++i) {
        int idx = tid + i * 256;
        int am = idx / (KC2 / 4);
        int ak = (idx % (KC2 / 4)) * 4;
        As[ak + 0][am] = aR[i].x; As[ak + 1][am] = aR[i].y;
        As[ak + 2][am] = aR[i].z; As[ak + 3][am] = aR[i].w;
        int bk = idx >> 4;
        int bn = (idx & 15) * 4;
        *(float4*)&Bs[bk][bn] = bR[i];
    }
    __syncthreads();

    unsigned long long acc[4][2];
    #pragma unroll
    for (int i = 0; i < 4; ++i) { acc[i][0] = 0ull; acc[i][1] = 0ull; }
    compute_loop<KC2>(As, Bs, acc);
    epilogue_red(g_y, n0, acc);

    if (tid == 0) cudaTriggerProgrammaticLaunchCompletion();
}

// Broadcast g_y over N=576 via TMA bulk stores; zero g_v for the next call.
// 576 blocks x 512 threads; PDL-synced against gemm2.
__global__ void __launch_bounds__(512)
bcast_kernel(float* __restrict__ out)
{
    __shared__ __align__(16) float ys[8 * C_DIM];   // 24 KB

    int b     = blockIdx.x / 9;
    int chunk = blockIdx.x % 9;
    const int tid = threadIdx.x;

    cudaGridDependencySynchronize();       // wait for gemm2's g_y

    const float4* ysrc = (const float4*)(g_y + b * C_DIM);
    #pragma unroll
    for (int i = tid; i < 8 * (C_DIM / 4); i += 512)
        ((float4*)ys)[i] = ysrc[i % (C_DIM / 4)];
    __syncthreads();
    asm volatile("fence.proxy.async.shared::cta;" ::: "memory");

    if (tid < 8) {
        uint32_t s = smem_u32(ys);
        float* g = out + ((size_t)b * N_SEQ + chunk * 64 + tid * 8) * C_DIM;
        asm volatile("cp.async.bulk.global.shared::cta.bulk_group [%0], [%1], %2;"
                     :: "l"(g), "r"(s), "n"(8 * C_DIM * 4) : "memory");
        asm volatile("cp.async.bulk.commit_group;" ::: "memory");
        asm volatile("cp.async.bulk.wait_group 0;" ::: "memory");
    }

    // zero g_v for the next call (first 192 blocks cover 12288 float4)
    if (blockIdx.x < 192 && tid < 64) {
        ((float4*)g_v)[blockIdx.x * 64 + tid] = make_float4(0.f, 0.f, 0.f, 0.f);
    }
}

extern "C" void kernel_launch(void* const* d_in, const int* in_sizes, int n_in,
                              void* d_out, int out_size)
{
    (void)in_sizes; (void)n_in; (void)out_size;
    // Inputs: image_patches, cnn_feature_vector, Wq, Wkv, Wp, bp
    const float* cnn = (const float*)d_in[1];
    const float* Wkv = (const float*)d_in[3];
    const float* Wp  = (const float*)d_in[4];
    const float* bp  = (const float*)d_in[5];
    float* out = (float*)d_out;

    gemm1_kernel<<<NT1 * KS1, 256>>>(cnn, Wkv, bp);   // 384 blocks

    cudaLaunchAttribute attr[1];
    attr[0].id = cudaLaunchAttributeProgrammaticStreamSerialization;
    attr[0].val.programmaticStreamSerializationAllowed = 1;

    {   // gemm2 with PDL
        cudaLaunchConfig_t cfg = {};
        cfg.gridDim  = dim3(NT2 * KS2, 1, 1);          // 192 blocks
        cfg.blockDim = dim3(256, 1, 1);
        cfg.attrs = attr;
        cfg.numAttrs = 1;
        cudaLaunchKernelEx(&cfg, gemm2_kernel, Wp);
    }
    {   // bcast with PDL
        cudaLaunchConfig_t cfg = {};
        cfg.gridDim  = dim3(B_SZ * 9, 1, 1);           // 576 blocks
        cfg.blockDim = dim3(512, 1, 1);
        cfg.attrs = attr;
        cfg.numAttrs = 1;
        cudaLaunchKernelEx(&cfg, bcast_kernel, out);
    }
}